// round 17
// baseline (speedup 1.0000x reference)
#include <cuda_runtime.h>
#include <cstddef>

// SegmentedPolynomialProductJit: out[e,k,u] = sum_{paths (i,j,k,c)} c * a[idx_a[e], i, u] * b[e, j, u]
// scatter-added into out[idx_out[e]].
// SA=4, SB=3, SC=4, U=32, paths: all (i,j), k=(i+j)%4, c=0.1*(i+1)+0.01*(j+1).
//
// Evidence log:
// R4:  baseline 150.9us, 1.0 GB HBM vs ~590 MB floor.
// R8:  __ldcs on b -> 129.0us, 775 MB. WIN.
// R12: a pinned (v8 evict_last) -> traffic unchanged. FAILED.
// R13: 128-thr blocks -> 126.0us kernel / 133.2 total. CHAMPION.
// R14: forced 40 regs, occ 63.8% -> slower. occupancy lever dead.
// R15: out pinned (red cache_hint evict_last) -> identical to R13. NEUTRAL.
//      All L2-hint levers exhausted; ~185 MB excess = capacity misses with
//      a(51MB)+out(51MB) oversubscribing effective L2.
// R16/R17: structural fix - two temporally-ordered passes over idx_a halves.
//      Per pass: a working set 25.6 MB; 25.6+51(out) fits L2 -> both random
//      sets resident. L2 persists across launches; passes serialize on stream.

#define SA 4
#define SB 3
#define SC 4
#define UE 32
#define A_ROW (SA * UE)   // 128 floats
#define B_ROW (SB * UE)   // 96 floats
#define O_ROW (SC * UE)   // 128 floats

// 8 threads per edge; each thread owns one float4 (4 consecutive u) across all segments.
// Processes only edges whose idx_a lies in [aLo, aHi).
__global__ __launch_bounds__(128) void spp_kernel(
    const float* __restrict__ a,
    const float* __restrict__ b,
    const int*   __restrict__ idx_a,
    const int*   __restrict__ idx_out,
    float*       __restrict__ out,
    int E, int aLo, int aHi)
{
    long long tid = (long long)blockIdx.x * blockDim.x + threadIdx.x;
    int e = (int)(tid >> 3);
    if (e >= E) return;
    int q = (int)(tid & 7);          // float4 index within a U=32 segment (8 quads)

    const int ia = __ldg(idx_a + e);
    if (ia < aLo || ia >= aHi) return;   // uniform across the 8 threads of this edge
    const int io = __ldg(idx_out + e);

    const float4* arow = reinterpret_cast<const float4*>(a) + (size_t)ia * (A_ROW / 4) + q;
    const float4* brow = reinterpret_cast<const float4*>(b) + (size_t)e  * (B_ROW / 4) + q;

    float4 A[SA], B[SB];
#pragma unroll
    for (int i = 0; i < SA; i++) A[i] = __ldg(arow + i * (UE / 4));      // reused: keep cached
#pragma unroll
    for (int j = 0; j < SB; j++) B[j] = __ldcs(brow + j * (UE / 4));     // read-once: streaming

    float4 O[SC];
#pragma unroll
    for (int k = 0; k < SC; k++) { O[k].x = 0.f; O[k].y = 0.f; O[k].z = 0.f; O[k].w = 0.f; }

#pragma unroll
    for (int i = 0; i < SA; i++) {
#pragma unroll
        for (int j = 0; j < SB; j++) {
            const int k = (i + j) & 3;
            const float c = 0.1f * (float)(i + 1) + 0.01f * (float)(j + 1);
            float cax = c * A[i].x;
            float cay = c * A[i].y;
            float caz = c * A[i].z;
            float caw = c * A[i].w;
            O[k].x = fmaf(cax, B[j].x, O[k].x);
            O[k].y = fmaf(cay, B[j].y, O[k].y);
            O[k].z = fmaf(caz, B[j].z, O[k].z);
            O[k].w = fmaf(caw, B[j].w, O[k].w);
        }
    }

    float* orow = out + (size_t)io * O_ROW + q * 4;
#pragma unroll
    for (int k = 0; k < SC; k++) {
        float* p = orow + k * UE;
        asm volatile("red.global.add.v4.f32 [%0], {%1, %2, %3, %4};"
                     :: "l"(p), "f"(O[k].x), "f"(O[k].y), "f"(O[k].z), "f"(O[k].w)
                     : "memory");
    }
}

extern "C" void kernel_launch(void* const* d_in, const int* in_sizes, int n_in,
                              void* d_out, int out_size)
{
    const float* a       = (const float*)d_in[0];
    const float* b       = (const float*)d_in[1];
    const int*   idx_a   = (const int*)d_in[2];
    const int*   idx_out = (const int*)d_in[3];
    float*       out     = (float*)d_out;

    const int E = in_sizes[1] / B_ROW;
    const int N = in_sizes[0] / A_ROW;   // number of a rows

    // Output buffer is poisoned by the harness; zero it (memset node is graph-capturable).
    cudaMemsetAsync(d_out, 0, (size_t)out_size * sizeof(float));

    const int threads = 128;
    const long long total = (long long)E * 8;
    const int blocks = (int)((total + threads - 1) / threads);

    const int half = (N + 1) / 2;
    // Pass 0: edges gathering from a[0, half) -> 25.6 MB a working set, L2-resident.
    spp_kernel<<<blocks, threads>>>(a, b, idx_a, idx_out, out, E, 0, half);
    // Pass 1: edges gathering from a[half, N). Stream-ordered after pass 0; L2 persists.
    spp_kernel<<<blocks, threads>>>(a, b, idx_a, idx_out, out, E, half, N);
}